// round 10
// baseline (speedup 1.0000x reference)
#include <cuda_runtime.h>
#include <cstdint>

// BDToGEConverter: out[b,s,p,d] = sum_k W[p,d,k] * x[b,s,k], W fixed-sparse
// (see prior rounds). R10 = champion R4 structure (flood + syncwarp +
// overwrite, streaming .cs policy everywhere) with 256-bit stores:
//   flood 5 x st.global.cs.v4.b64 per lane, overwrite = 18 lanes x 32B.

static constexpr int BD_DIM    = 512;
static constexpr int ROW_BYTES = 5120;         // 1280 floats per (b,s) row
static constexpr int THREADS   = 256;          // 8 warps = 8 rows per block

typedef unsigned long long u64;

__device__ __forceinline__ u64 pack2(float lo, float hi) {
    return (u64)__float_as_uint(lo) | ((u64)__float_as_uint(hi) << 32);
}

__device__ __forceinline__ void st256cs(char* p, u64 v0, u64 v1, u64 v2, u64 v3) {
    asm volatile("st.global.cs.v4.b64 [%0], {%1,%2,%3,%4};"
                 :: "l"(p), "l"(v0), "l"(v1), "l"(v2), "l"(v3) : "memory");
}

__global__ __launch_bounds__(THREADS)
void bd2ge_cs256(const float* __restrict__ x, float* __restrict__ out)
{
    const unsigned FULL = 0xffffffffu;
    const int t    = threadIdx.x;
    const int warp = t >> 5;
    const int lane = t & 31;

    const long long row = (long long)blockIdx.x * 8 + warp;
    const float*    g   = x + row * (long long)BD_DIM;

    // ---- per-lane input loads (issued before the store flood)
    float a0 = 0.f, a1 = 0.f, a2 = 0.f, a3 = 0.f, vop = 0.f;
    if (lane < 16) {
        const float m = (float)lane;
        a0 = __ldg(g + 64  + lane) * m;
        a1 = __ldg(g + 80  + lane) * m;
        a2 = __ldg(g + 96  + lane) * m;
        a3 = __ldg(g + 112 + lane) * m;
    } else if (lane < 26) {
        vop = __ldg(g + 10 + (lane - 16));
    }

    // ---- zero-flood: 5 x 32B streaming stores per lane, immediate offsets
    char* rowb = reinterpret_cast<char*>(out) + row * (long long)ROW_BYTES;
    char* pb   = rowb + lane * 32;
    #pragma unroll
    for (int i = 0; i < 5; ++i)
        st256cs(pb + i * 1024, 0, 0, 0, 0);

    // ---- dot reductions + broadcasts (overlap with stores in flight)
    #pragma unroll
    for (int o = 8; o > 0; o >>= 1) {
        a0 += __shfl_xor_sync(FULL, a0, o, 16);
        a1 += __shfl_xor_sync(FULL, a1, o, 16);
        a2 += __shfl_xor_sync(FULL, a2, o, 16);
        a3 += __shfl_xor_sync(FULL, a3, o, 16);
    }
    a0 = __shfl_sync(FULL, a0, 0);
    a1 = __shfl_sync(FULL, a1, 0);
    a2 = __shfl_sync(FULL, a2, 0);
    a3 = __shfl_sync(FULL, a3, 0);
    float xv[10];                        // xv[j] = x[10+j]
    #pragma unroll
    for (int j = 0; j < 10; ++j)
        xv[j] = __shfl_sync(FULL, vop, 16 + j);

    // packed special-chunk payloads (26 nonzeros live in 18 aligned 32B chunks)
    const u64 d0  = pack2(a0, a2);                  // p0: d0,d1
    const u64 d1  = pack2(a1, a3);                  // p1: d0,d1
    const u64 s3a = pack2(0.f,  xv[6]);             // d24=0, d25=x16
    const u64 s3b = pack2(xv[7], xv[0]);            // d26=x17, d27=x10
    const u64 s3c = pack2(xv[1], xv[2]);            // d28, d29
    const u64 s3d = pack2(xv[3], xv[4]);            // d30, d31
    const u64 s4a = pack2(xv[5], xv[8]);            // d32, d33
    const u64 s4b = pack2(xv[9], 0.f);              // d34, d35=0

    __syncwarp();                       // order zero-flood before overwrites

    if (lane == 0) {
        st256cs(rowb, d0, 0, 0, 0);                          // p0 d0..7
    } else if (lane == 1) {
        st256cs(rowb + 640, d1, 0, 0, 0);                    // p1 d0..7
    } else if (lane < 10) {                                  // p chunk3: d24..31
        st256cs(rowb + (lane - 2) * 640 + 96, s3a, s3b, s3c, s3d);
    } else if (lane < 18) {                                  // p chunk4: d32..39
        st256cs(rowb + (lane - 10) * 640 + 128, s4a, s4b, 0, 0);
    }
}

extern "C" void kernel_launch(void* const* d_in, const int* in_sizes, int n_in,
                              void* d_out, int out_size)
{
    const float* x = (const float*)d_in[0];   // x_bd [B,S,512]
    float* out = (float*)d_out;               // [B,S,8,160]

    int n_rows = in_sizes[0] / BD_DIM;        // B*S = 32768
    int grid   = n_rows / 8;                  // 4096 blocks, warp-per-row

    bd2ge_cs256<<<grid, THREADS>>>(x, out);
}

// round 11
// speedup vs baseline: 1.1491x; 1.1491x over previous
#include <cuda_runtime.h>
#include <cstdint>

// BDToGEConverter: out[b,s,p,d] = sum_k W[p,d,k] * x[b,s,k], W fixed-sparse:
//   out[.,0,0]=Σ j·x[64+j]  out[.,0,1]=Σ j·x[96+j]
//   out[.,1,0]=Σ j·x[80+j]  out[.,1,1]=Σ j·x[112+j]       (j=0..15)
//   for all p: x10→d27 x11→d28 x12→d29 x13→d30 x14→d31 x15→d32
//              x16→d25 x17→d26 x18→d33 x19→d34 ; all else 0.
//
// R11 = exact A/A resubmission of champion R4 (wall 27.1us) to separate
// kernel effect from run-environment variance. Warp-per-row, 10x 128-bit
// .cs zero-flood per lane, syncwarp, 26-lane special overwrite.

static constexpr int BD_DIM   = 512;
static constexpr int ROW_OUT4 = 320;     // float4 per (b,s) row
static constexpr int THREADS  = 256;     // 8 warps = 8 rows per block

__global__ __launch_bounds__(THREADS)
void bd2ge_reg(const float* __restrict__ x, float* __restrict__ out)
{
    const unsigned FULL = 0xffffffffu;
    const int t    = threadIdx.x;
    const int warp = t >> 5;
    const int lane = t & 31;

    const long long row = (long long)blockIdx.x * 8 + warp;
    const float*    g   = x + row * (long long)BD_DIM;

    // ---- per-lane input loads (issued before the store flood)
    float a0 = 0.f, a1 = 0.f, a2 = 0.f, a3 = 0.f, vop = 0.f;
    if (lane < 16) {
        const float m = (float)lane;
        a0 = __ldg(g + 64  + lane) * m;
        a1 = __ldg(g + 80  + lane) * m;
        a2 = __ldg(g + 96  + lane) * m;
        a3 = __ldg(g + 112 + lane) * m;
    } else if (lane < 26) {
        vop = __ldg(g + 10 + (lane - 16));
    }

    // ---- flood the row with zeros: 10 immediate-offset streaming stores/lane
    float4* rowb = reinterpret_cast<float4*>(out) + row * ROW_OUT4 + lane;
    const float4 z = make_float4(0.f, 0.f, 0.f, 0.f);
    #pragma unroll
    for (int i = 0; i < 10; ++i)
        __stcs(rowb + i * 32, z);

    // ---- reductions + broadcasts (overlap with stores in flight)
    #pragma unroll
    for (int o = 8; o > 0; o >>= 1) {
        a0 += __shfl_xor_sync(FULL, a0, o, 16);
        a1 += __shfl_xor_sync(FULL, a1, o, 16);
        a2 += __shfl_xor_sync(FULL, a2, o, 16);
        a3 += __shfl_xor_sync(FULL, a3, o, 16);
    }
    float xv[10];                       // xv[j] = x[10+j], lane 16+j holds it
    #pragma unroll
    for (int j = 0; j < 10; ++j)
        xv[j] = __shfl_sync(FULL, vop, 16 + j);

    // ---- compose this lane's special float4 (26 nonzero slots per row)
    float4 sv = z;
    int    w  = 0;
    if (lane == 0)       { sv = make_float4(a0, a2, 0.f, 0.f);             w = 0; }
    else if (lane == 1)  { sv = make_float4(a1, a3, 0.f, 0.f);             w = 40; }
    else if (lane < 10)  { sv = make_float4(0.f, xv[6], xv[7], xv[0]);     w = (lane - 2) * 40 + 6; }   // d 24..27
    else if (lane < 18)  { sv = make_float4(xv[1], xv[2], xv[3], xv[4]);   w = (lane - 10) * 40 + 7; }  // d 28..31
    else if (lane < 26)  { sv = make_float4(xv[5], xv[8], xv[9], 0.f);     w = (lane - 18) * 40 + 8; }  // d 32..35

    __syncwarp();                       // order zero-flood before overwrites
    if (lane < 26)
        __stcs(reinterpret_cast<float4*>(out) + row * ROW_OUT4 + w, sv);
}

extern "C" void kernel_launch(void* const* d_in, const int* in_sizes, int n_in,
                              void* d_out, int out_size)
{
    const float* x = (const float*)d_in[0];   // x_bd [B,S,512]
    float* out = (float*)d_out;               // [B,S,8,160]

    int n_rows = in_sizes[0] / BD_DIM;        // B*S = 32768
    int grid   = n_rows / 8;                  // 4096 blocks, warp-per-row

    bd2ge_reg<<<grid, THREADS>>>(x, out);
}